// round 2
// baseline (speedup 1.0000x reference)
#include <cuda_runtime.h>
#include <math.h>

// NuclearLattice: D=3, W=64 -> box [-32,32]^3, spin bound [-0.5,0.5]
// V0=10, VS=2, A_RANGE=2 (-> -1/A_RANGE^2 = -0.25), KC=1.44, EPS=1e-6, PAULI_D2=1e-6

#define TILE 256

__device__ double g_acc;
__device__ int    g_blocked;

__global__ void nl_init_kernel() {
    g_acc = 0.0;
    g_blocked = 0;
}

__global__ __launch_bounds__(TILE) void nl_pair_kernel(const float* __restrict__ states, int A) {
    const int bx = blockIdx.x;   // i-tile
    const int by = blockIdx.y;   // j-tile
    if (by < bx) return;         // triangular: only j-tile >= i-tile
    const bool diag = (bx == by);

    __shared__ float sx[TILE], sy[TILE], sz[TILE], ssp[TILE], sq[TILE];

    const int tid = threadIdx.x;
    const int i   = bx * TILE + tid;
    const bool vi = (i < A);

    // i-atom registers; padded atoms at +inf-ish with zero spin/charge -> zero energy
    float xi = 1e18f, yi = 1e18f, zi = 1e18f, spi = 0.0f, qi = 0.0f;
    if (vi) {
        const float* s = states + (size_t)i * 5;
        xi  = s[0];
        yi  = s[1];
        zi  = s[2];
        spi = s[3];
        qi  = s[4] + 0.5f;   // q = iso + 0.5
    }
    const float tsp = 2.0f * spi;     // for coef = fma(2*spi, bsp, -10)
    const float aq  = 1.44f * qi;     // for coul = aq * bq * rsqrt(d2+eps)

    // Bounds check (blocked_b) once per atom, on diagonal blocks:
    // first 4 columns vs [-32,32]^3 x [-0.5,0.5] (iso column excluded).
    if (vi && diag) {
        bool bad = (xi  < -32.0f) || (xi  > 32.0f) ||
                   (yi  < -32.0f) || (yi  > 32.0f) ||
                   (zi  < -32.0f) || (zi  > 32.0f) ||
                   (spi < -0.5f)  || (spi > 0.5f);
        if (bad) atomicOr(&g_blocked, 1);
    }

    // j-tile -> SoA shared memory; padding at -1e18 with zero spin/charge
    const int jbase = by * TILE;
    {
        const int j = jbase + tid;
        if (j < A) {
            const float* s = states + (size_t)j * 5;
            sx[tid]  = s[0];
            sy[tid]  = s[1];
            sz[tid]  = s[2];
            ssp[tid] = s[3];
            sq[tid]  = s[4] + 0.5f;
        } else {
            sx[tid] = -1e18f; sy[tid] = -1e18f; sz[tid] = -1e18f;
            ssp[tid] = 0.0f;  sq[tid] = 0.0f;
        }
    }
    __syncthreads();

    float acc = 0.0f;
    int   pcount = 0;

    #pragma unroll 8
    for (int jj = 0; jj < TILE; jj++) {
        const float dx = xi - sx[jj];
        const float dy = yi - sy[jj];
        const float dz = zi - sz[jj];
        const float d2 = fmaf(dx, dx, fmaf(dy, dy, dz * dz));

        // 5-dim Pauli distance (iso diff == q diff since both shifted by +0.5)
        const float ds  = spi - ssp[jj];
        const float dqv = qi  - sq[jj];
        const float d2s = fmaf(ds, ds, fmaf(dqv, dqv, d2));

        const float g    = __expf(-0.25f * d2);            // exp(-d2/A_RANGE^2)
        const float coef = fmaf(tsp, ssp[jj], -10.0f);     // -V0 + VS*ss
        const float coul = aq * sq[jj] * rsqrtf(d2 + 1e-6f);
        acc += fmaf(coef, g, coul);
        pcount += (d2s < 1e-6f) ? 1 : 0;
    }

    // Diagonal blocks included the self pair once: subtract it analytically.
    // e_self = (-10 + 2*sp^2)*exp(0) + 1.44*q^2*rsqrt(eps); self d2s==0 -> one pauli hit.
    if (diag && vi) {
        const float e_self = fmaf(tsp, spi, -10.0f) + aq * qi * rsqrtf(1e-6f);
        acc -= e_self;
    }
    const int pthresh = (diag && vi) ? 1 : 0;
    if (pcount > pthresh) atomicOr(&g_blocked, 1);

    // Off-diagonal tiles: each unordered pair counted once (weight 1).
    // Diagonal tiles: both orders counted (weight 0.5).
    if (diag) acc *= 0.5f;

    // Reduce: fp32 per-thread -> double warp reduce -> double block reduce -> one atomic
    double v = (double)acc;
    #pragma unroll
    for (int off = 16; off > 0; off >>= 1)
        v += __shfl_down_sync(0xffffffffu, v, off);

    __shared__ double wsum[TILE / 32];
    const int lane = tid & 31;
    const int warp = tid >> 5;
    if (lane == 0) wsum[warp] = v;
    __syncthreads();

    if (warp == 0) {
        v = (lane < TILE / 32) ? wsum[lane] : 0.0;
        #pragma unroll
        for (int off = (TILE / 32) / 2; off > 0; off >>= 1)
            v += __shfl_down_sync(0xffffffffu, v, off);
        if (lane == 0) atomicAdd(&g_acc, v);
    }
}

__global__ void nl_fin_kernel(float* __restrict__ out) {
    out[0] = g_blocked ? INFINITY : (float)g_acc;
}

extern "C" void kernel_launch(void* const* d_in, const int* in_sizes, int n_in,
                              void* d_out, int out_size) {
    const float* states = (const float*)d_in[0];
    const int A = in_sizes[0] / 5;

    nl_init_kernel<<<1, 1>>>();

    const int tiles = (A + TILE - 1) / TILE;
    dim3 grid(tiles, tiles);
    nl_pair_kernel<<<grid, TILE>>>(states, A);

    nl_fin_kernel<<<1, 1>>>((float*)d_out);
}

// round 3
// speedup vs baseline: 1.8615x; 1.8615x over previous
#include <cuda_runtime.h>
#include <math.h>

// NuclearLattice: D=3, W=64 -> box [-32,32]^3, spin in [-0.5,0.5]
// V0=10, VS=2, A_RANGE=2, KC=1.44, EPS=1e-6, PAULI_D2=1e-6
// gauss = exp(-d2/4) = exp2(d2 * -0.25*log2(e))

#define TILE 128

__device__ double       g_acc     = 0.0;
__device__ int          g_blocked = 0;
__device__ unsigned int g_done    = 0;

template<bool DIAG, bool COUL>
__device__ __forceinline__ void pair_loop(
    const float4* __restrict__ sa,   // {-2x, -2y, -2z, psq}
    const float4* __restrict__ sb,   // {sp, c, q, 0}
    float xi, float yi, float zi, float psqi,
    float tsp, float ci, float aq, int tid,
    float& acc, int& pcount, float& pmin)
{
    #pragma unroll 8
    for (int jj = 0; jj < TILE; jj++) {
        const float4 a = sa[jj];
        const float4 b = sb[jj];

        // d2 = psq_i + psq_j - 2*dot  (reference's own formula), clamped >= 0
        float t  = fmaf(a.z, zi, a.w);
        t        = fmaf(a.y, yi, t);
        t        = fmaf(a.x, xi, t);
        float d2 = fmaxf(t + psqi, 0.0f);

        // Pauli 5-dim distance via collapsed class scalar c = sp + 2q
        const float dc  = ci - b.y;
        const float d2c = fmaf(dc, dc, d2);

        float g;
        asm("ex2.approx.f32 %0, %1;" : "=f"(g) : "f"(d2 * -0.36067376f));
        const float coef = fmaf(tsp, b.x, -10.0f);   // -V0 + VS*ss

        float r = 0.0f, cq = 0.0f;
        if (COUL) {
            const float d2e = d2 + 1e-6f;
            asm("rsqrt.approx.f32 %0, %1;" : "=f"(r) : "f"(d2e));
            cq = aq * b.z;                           // 1.44*qi*qj
        }

        if (DIAG) {
            if (jj != tid) {                         // exclude self pair
                acc = fmaf(coef, g, acc);
                if (COUL) acc = fmaf(cq, r, acc);
                pcount += (d2c < 1e-6f) ? 1 : 0;
            }
        } else {
            acc = fmaf(coef, g, acc);
            if (COUL) acc = fmaf(cq, r, acc);
            pmin = fminf(pmin, d2c);
        }
    }
}

__global__ __launch_bounds__(TILE) void nl_kernel(
    const float* __restrict__ states, int A, int nblocks, float* __restrict__ out)
{
    // Decode triangular block index k -> (bx <= by)
    const int k = blockIdx.x;
    int by = (int)((sqrtf(8.0f * (float)k + 1.0f) - 1.0f) * 0.5f);
    while ((by + 1) * (by + 2) / 2 <= k) by++;
    while (by * (by + 1) / 2 > k)       by--;
    const int bx = k - by * (by + 1) / 2;
    const bool diag = (bx == by);

    __shared__ float4 sa[TILE];
    __shared__ float4 sb[TILE];

    const int tid = threadIdx.x;
    const int i   = bx * TILE + tid;
    const bool vi = (i < A);

    // i-atom registers (padding pushed far away with zero spin/charge)
    float xi = 1e18f, yi = 1e18f, zi = 1e18f, spi = 0.0f, qi = 0.0f;
    if (vi) {
        const float* s = states + (size_t)i * 5;
        xi = s[0]; yi = s[1]; zi = s[2];
        spi = s[3];
        qi  = s[4] + 0.5f;
    }
    const float psqi = fmaf(xi, xi, fmaf(yi, yi, zi * zi));
    const float tsp  = 2.0f * spi;
    const float ci   = fmaf(2.0f, qi, spi);   // class scalar
    const float aq   = 1.44f * qi;

    // Bounds check once per atom (each atom is in exactly one diagonal block)
    if (vi && diag) {
        const bool bad = (xi  < -32.0f) || (xi  > 32.0f) ||
                         (yi  < -32.0f) || (yi  > 32.0f) ||
                         (zi  < -32.0f) || (zi  > 32.0f) ||
                         (spi < -0.5f)  || (spi > 0.5f);
        if (bad) atomicOr(&g_blocked, 1);
    }

    // j-tile -> smem (SoA float4), pre-scaled for the fused-dot d2
    float qj_own = 0.0f;
    {
        const int j = by * TILE + tid;
        float xj = -1e18f, yj = -1e18f, zj = -1e18f, spj = 0.0f, qj = 0.0f;
        if (j < A) {
            const float* s = states + (size_t)j * 5;
            xj = s[0]; yj = s[1]; zj = s[2];
            spj = s[3];
            qj  = s[4] + 0.5f;
        }
        const float psqj = fmaf(xj, xj, fmaf(yj, yj, zj * zj));
        sa[tid] = make_float4(-2.0f * xj, -2.0f * yj, -2.0f * zj, psqj);
        sb[tid] = make_float4(spj, fmaf(2.0f, qj, spj), qj, 0.0f);
        qj_own  = qj;
    }

    // Runtime-uniform Coulomb flag: any charge in i-tile AND any in j-tile
    const int anyQi = __syncthreads_or(qi != 0.0f ? 1 : 0);
    const int anyQj = __syncthreads_or(qj_own != 0.0f ? 1 : 0);
    const bool coul = (anyQi != 0) && (anyQj != 0);

    float acc   = 0.0f;
    int   pcount = 0;
    float pmin  = 1e30f;

    if (diag) {
        if (coul) pair_loop<true,  true >(sa, sb, xi, yi, zi, psqi, tsp, ci, aq, tid, acc, pcount, pmin);
        else      pair_loop<true,  false>(sa, sb, xi, yi, zi, psqi, tsp, ci, aq, tid, acc, pcount, pmin);
        acc *= 0.5f;   // both orders counted within the tile
    } else {
        if (coul) pair_loop<false, true >(sa, sb, xi, yi, zi, psqi, tsp, ci, aq, tid, acc, pcount, pmin);
        else      pair_loop<false, false>(sa, sb, xi, yi, zi, psqi, tsp, ci, aq, tid, acc, pcount, pmin);
    }

    const bool pauli = diag ? (pcount > 0) : (pmin < 1e-6f);
    if (pauli) atomicOr(&g_blocked, 1);

    // Reduce: fp32 per-thread -> double warp -> double block -> one atomicAdd
    double v = (double)acc;
    #pragma unroll
    for (int off = 16; off > 0; off >>= 1)
        v += __shfl_down_sync(0xffffffffu, v, off);

    __shared__ double wsum[TILE / 32];
    const int lane = tid & 31;
    const int warp = tid >> 5;
    if (lane == 0) wsum[warp] = v;
    __syncthreads();

    if (warp == 0) {
        v = (lane < TILE / 32) ? wsum[lane] : 0.0;
        #pragma unroll
        for (int off = (TILE / 32) / 2; off > 0; off >>= 1)
            v += __shfl_down_sync(0xffffffffu, v, off);

        if (lane == 0) {
            atomicAdd(&g_acc, v);
            __threadfence();
            const unsigned t = atomicAdd(&g_done, 1u);
            if (t == (unsigned)nblocks - 1u) {
                // Last block: publish result and reset state for next graph replay
                const double e  = atomicAdd(&g_acc, 0.0);
                const int    bl = atomicOr(&g_blocked, 0);
                out[0] = bl ? INFINITY : (float)e;
                g_acc     = 0.0;
                g_blocked = 0;
                __threadfence();
                g_done = 0;
            }
        }
    }
}

extern "C" void kernel_launch(void* const* d_in, const int* in_sizes, int n_in,
                              void* d_out, int out_size) {
    const float* states = (const float*)d_in[0];
    const int A = in_sizes[0] / 5;

    const int tiles   = (A + TILE - 1) / TILE;
    const int nblocks = tiles * (tiles + 1) / 2;

    nl_kernel<<<nblocks, TILE>>>(states, A, nblocks, (float*)d_out);
}